// round 11
// baseline (speedup 1.0000x reference)
#include <cuda_runtime.h>
#include <cstdint>

#define S_LEN 2048
#define BATCH 128
#define IN_DIM 64
#define HID 128
#define G4 512
#define OUT_DIM 64
#define NGROUP 32
#define CPG 4
#define BG 4
#define NCTA (NGROUP * CPG)

// ---- static device scratch ----
__device__ float g_Xp[(size_t)S_LEN * BATCH * G4];   // [s][b][n]
__device__ float g_hs[(size_t)S_LEN * BATCH * HID];  // [s][b][h]
__device__ int g_dummy;

#define OUT_SMEM ((128 * 136 + 128 * 65) * 4)

__device__ __forceinline__ float sigf(float v) {
    return __fdividef(1.f, 1.f + __expf(-v));
}
__device__ __forceinline__ float tanhf_fast(float x) {
    float cx = fminf(fmaxf(x, -15.f), 15.f);
    float e = __expf(2.f * cx);
    return __fdividef(e - 1.f, e + 1.f);
}

__device__ __forceinline__ uint32_t smem_u32(const void* p) {
    uint32_t a;
    asm("{ .reg .u64 t; cvta.to.shared.u64 t, %1; cvt.u32.u64 %0, t; }" : "=r"(a) : "l"(p));
    return a;
}
__device__ __forceinline__ uint32_t mapa_u32(uint32_t local_addr, int rank) {
    uint32_t r;
    asm("mapa.shared::cluster.u32 %0, %1, %2;" : "=r"(r) : "r"(local_addr), "r"(rank));
    return r;
}
#define CLUSTER_SYNC_() do { \
    asm volatile("barrier.cluster.arrive.aligned;" ::: "memory"); \
    asm volatile("barrier.cluster.wait.aligned;" ::: "memory"); \
} while (0)

#define MBAR_INIT(addr, cnt) \
    asm volatile("mbarrier.init.shared.b64 [%0], %1;" :: "r"(addr), "r"(cnt) : "memory")
#define MBAR_ARM(addr, bytes) \
    asm volatile("mbarrier.arrive.expect_tx.shared.b64 _, [%0], %1;" :: "r"(addr), "r"(bytes) : "memory")
#define MBAR_WAIT(addr, parity) do { \
    asm volatile("{\n\t.reg .pred P1;\n\t" \
        "WAIT_%=:\n\t" \
        "mbarrier.try_wait.parity.acquire.cta.shared::cta.b64 P1, [%0], %1, 0x989680;\n\t" \
        "@P1 bra.uni DONE_%=;\n\t" \
        "bra.uni WAIT_%=;\n\t" \
        "DONE_%=:\n\t}" \
        :: "r"(addr), "r"(parity) : "memory"); \
} while (0)

__device__ __forceinline__ void st_async_f32(uint32_t daddr, uint32_t dmbar, float v) {
    asm volatile("st.async.shared::cluster.mbarrier::complete_tx::bytes.f32 [%0], %1, [%2];"
                 :: "r"(daddr), "f"(v), "r"(dmbar) : "memory");
}
__device__ __forceinline__ void st_async_v2f32(uint32_t daddr, uint32_t dmbar, float a, float b) {
    asm volatile("st.async.shared::cluster.mbarrier::complete_tx::bytes.v2.f32 [%0], {%1, %2}, [%3];"
                 :: "r"(daddr), "f"(a), "f"(b), "r"(dmbar) : "memory");
}

__device__ __forceinline__ void ffma2(unsigned long long& d, unsigned long long a, unsigned long long b) {
    asm("fma.rn.f32x2 %0, %1, %2, %0;" : "+l"(d) : "l"(a), "l"(b));
}
__device__ __forceinline__ unsigned long long pack2(float a, float b) {
    unsigned long long p;
    asm("mov.b64 %0, {%1, %2};" : "=l"(p) : "f"(a), "f"(b));
    return p;
}
__device__ __forceinline__ float sum2(unsigned long long p) {
    float lo, hi;
    asm("mov.b64 {%0, %1}, %2;" : "=f"(lo), "=f"(hi) : "l"(p));
    return lo + hi;
}

// ---- dummy: keeps rec_kernel at process launch #4 for ncu capture ----
__global__ void dummy_kernel(int v) {
    if (threadIdx.x == 0 && blockIdx.x == 0) g_dummy = v;
}

// ---- Kernel 1: Xp[s][b][n] = b_out[n] + sum_i x[b][i][s] * Wx_out[i][n] ----
__global__ __launch_bounds__(256) void xproj_kernel(const float* __restrict__ x,
                                                    const float* __restrict__ Wx,
                                                    const float* __restrict__ bo) {
    __shared__ float xs[IN_DIM * 33];
    const int s = blockIdx.x;
    const int b0 = blockIdx.y * 32;
    const int t = threadIdx.x;
    const int b = t & 31;
    const int n0 = (t >> 5) * 64;

    for (int q = t; q < 32 * IN_DIM; q += 256) {
        int bb = q >> 6, i = q & 63;
        xs[i * 33 + bb] = x[((size_t)(b0 + bb) * IN_DIM + i) * S_LEN + s];
    }
    __syncthreads();

    float acc[64];
#pragma unroll
    for (int j = 0; j < 64; j++) acc[j] = 0.f;
#pragma unroll 2
    for (int k = 0; k < IN_DIM; k++) {
        float xv = xs[k * 33 + b];
        const float4* wr = (const float4*)(Wx + (size_t)k * G4 + n0);
#pragma unroll
        for (int j4 = 0; j4 < 16; j4++) {
            float4 w = __ldg(&wr[j4]);
            acc[4 * j4 + 0] = fmaf(xv, w.x, acc[4 * j4 + 0]);
            acc[4 * j4 + 1] = fmaf(xv, w.y, acc[4 * j4 + 1]);
            acc[4 * j4 + 2] = fmaf(xv, w.z, acc[4 * j4 + 2]);
            acc[4 * j4 + 3] = fmaf(xv, w.w, acc[4 * j4 + 3]);
        }
    }
#pragma unroll
    for (int j = 0; j < 64; j++) {
        g_Xp[((size_t)s * BATCH + b0 + b) * G4 + n0 + j] = acc[j] + __ldg(&bo[n0 + j]);
    }
}

// ---- Kernel 2: persistent recurrence; cluster of 4 CTAs = 1 group (4 batch rows).
//      512 threads: thread (j = t>>2, kq = t&3) owns gate col j, K-quarter kq.
//      96 weight regs/thread, 4 warps/SMSP, butterfly reduction over kq. ----
__global__ __launch_bounds__(512, 1) __cluster_dims__(CPG, 1, 1)
void rec_kernel(const float* __restrict__ Wh_out,
                const float* __restrict__ Wx_in,
                const float* __restrict__ Wh_in,
                const float* __restrict__ b_in) {
    __shared__ __align__(16) float sh_h[BG * 2 * 68];     // staged h  [r][2 x 68]
    __shared__ __align__(16) float sh_xh[BG * 4 * 68];    // staged xh [r][4 x 68] (k'=2h interleave)
    __shared__ __align__(16) float sg[BG * 128];          // gates [r][hc][gate]
    __shared__ __align__(8) unsigned long long mbars[2];  // [0]=xh, [1]=h
    __shared__ uint32_t ptab[CPG * 4];                    // per rank: xh, h, bx, bh

    const int cta = blockIdx.x;
    const int g   = cta >> 2;
    const int t   = threadIdx.x;
    const int j   = t >> 2;            // gate column 0..127
    const int kq  = t & 3;             // K-quarter
    uint32_t cs;
    asm("mov.u32 %0, %%cluster_ctarank;" : "=r"(cs));
    const int gcol = (j >> 5) * 128 + (int)cs * 32 + (j & 31);
    const int sgi  = (j & 31) * 4 + (j >> 5);   // transposed gate slot

    // ---- register-resident weights, K-quarter kq ----
    unsigned long long wo[16];   // outer: k = kq*32 + 2q -> {Wh_out[k], Wh_out[k+1]}
    unsigned long long wi[32];   // inner: h = kq*32 + q -> {Wx_in[h], Wh_in[h]}
    {
        const float* wbase = Wh_out + (size_t)(kq * 32) * G4 + gcol;
#pragma unroll
        for (int q = 0; q < 16; q++)
            wo[q] = pack2(wbase[(size_t)(2 * q) * G4], wbase[(size_t)(2 * q + 1) * G4]);
        const int hh0 = kq * 32;
#pragma unroll
        for (int q = 0; q < 32; q++)
            wi[q] = pack2(Wx_in[(size_t)(hh0 + q) * G4 + gcol],
                          Wh_in[(size_t)(hh0 + q) * G4 + gcol]);
    }
    const float bin = b_in[gcol];

    // peer address table + mbarrier init/arm
    if (t < CPG) {
        ptab[t * 4 + 0] = mapa_u32(smem_u32(sh_xh), t);
        ptab[t * 4 + 1] = mapa_u32(smem_u32(sh_h), t);
        ptab[t * 4 + 2] = mapa_u32(smem_u32(&mbars[0]), t);
        ptab[t * 4 + 3] = mapa_u32(smem_u32(&mbars[1]), t);
    }
    const uint32_t bx_loc = smem_u32(&mbars[0]);
    const uint32_t bh_loc = smem_u32(&mbars[1]);
    if (t == 0) {
        MBAR_INIT(bx_loc, 1);
        MBAR_INIT(bh_loc, 1);
        MBAR_ARM(bx_loc, 3072u);   // 3 peers x 128 x 8B
        MBAR_ARM(bh_loc, 1536u);   // 3 peers x 128 x 4B
    }
    for (int q = t; q < BG * 2 * 68; q += 512) sh_h[q] = 0.f;  // h0 = 0
    __syncthreads();
    CLUSTER_SYNC_();

    // owner role (t < 128): batch row bl, own hidden col
    const int bl = t >> 5, hc = t & 31;
    const int h_own = (int)cs * 32 + hc;
    const int kxi = 2 * h_own;
    const int loc_x = bl * 272 + (kxi >> 6) * 68 + (kxi & 63);
    const int loc_h = bl * 136 + (h_own >> 6) * 68 + (h_own & 63);
    const uint32_t offb_x = (uint32_t)loc_x * 4u;
    const uint32_t offb_h = (uint32_t)loc_h * 4u;
    float c_reg = 0.f, cn_reg = 0.f, o_reg = 0.f;

    // per-thread Xp pointer: row kq of the group's 4 batch rows
    const float* xp_base = g_Xp + (size_t)(g * BG + kq) * G4 + gcol;
    // GEMM staging bases for this thread's K-quarter
    const int ob = (kq >> 1) * 68 + (kq & 1) * 32;   // outer: k in [kq*32, kq*32+32)
    const int ib = kq * 68;                          // inner: k' in [kq*64, kq*64+64)

    for (int s = 0; s < S_LEN; s++) {
        const uint32_t par = (uint32_t)(s & 1);
        float xpv = __ldcs(xp_base + (size_t)s * BATCH * G4);

        // ---- outer GEMM: quarter kq, 4 rows ----
        unsigned long long a0 = 0ull, a1 = 0ull, a2 = 0ull, a3 = 0ull;
        {
            const ulonglong2* h0 = (const ulonglong2*)(sh_h + 0 * 136 + ob);
            const ulonglong2* h1 = (const ulonglong2*)(sh_h + 1 * 136 + ob);
            const ulonglong2* h2 = (const ulonglong2*)(sh_h + 2 * 136 + ob);
            const ulonglong2* h3 = (const ulonglong2*)(sh_h + 3 * 136 + ob);
#pragma unroll
            for (int q2 = 0; q2 < 8; q2++) {
                ulonglong2 x0 = h0[q2], x1 = h1[q2], x2 = h2[q2], x3 = h3[q2];
                unsigned long long wA = wo[2 * q2], wB = wo[2 * q2 + 1];
                ffma2(a0, x0.x, wA); ffma2(a0, x0.y, wB);
                ffma2(a1, x1.x, wA); ffma2(a1, x1.y, wB);
                ffma2(a2, x2.x, wA); ffma2(a2, x2.y, wB);
                ffma2(a3, x3.x, wA); ffma2(a3, x3.y, wB);
            }
        }
        {
            float s0 = sum2(a0), s1 = sum2(a1), s2 = sum2(a2), s3 = sum2(a3);
            s0 += __shfl_xor_sync(0xffffffffu, s0, 1);
            s1 += __shfl_xor_sync(0xffffffffu, s1, 1);
            s2 += __shfl_xor_sync(0xffffffffu, s2, 1);
            s3 += __shfl_xor_sync(0xffffffffu, s3, 1);
            s0 += __shfl_xor_sync(0xffffffffu, s0, 2);
            s1 += __shfl_xor_sync(0xffffffffu, s1, 2);
            s2 += __shfl_xor_sync(0xffffffffu, s2, 2);
            s3 += __shfl_xor_sync(0xffffffffu, s3, 2);
            float sv = (kq == 0) ? s0 : ((kq == 1) ? s1 : ((kq == 2) ? s2 : s3));
            sg[kq * 128 + sgi] = sv + xpv;
        }
        __syncthreads();

        // ---- elementwise 1: float4 gate read; own (x_in,h_in) local, 3 peers st.async ----
        if (t < 128) {
            float4 gv = *(const float4*)(sg + bl * 128 + hc * 4);  // {i, f, o, g}
            float i_ = sigf(gv.x);
            float f_ = sigf(gv.y);
            o_reg    = sigf(gv.z);
            float g_ = tanhf_fast(gv.w);
            float xin = i_ * g_;
            float hin = f_ * c_reg;
            *(float2*)(sh_xh + loc_x) = make_float2(xin, hin);
#pragma unroll
            for (int r = 0; r < CPG; r++)
                if (r != (int)cs)
                    st_async_v2f32(ptab[r * 4 + 0] + offb_x, ptab[r * 4 + 2], xin, hin);
        }
        __syncthreads();   // own xh visible
        MBAR_WAIT(bx_loc, par);
        if (t == 0) MBAR_ARM(bx_loc, 3072u);

        // ---- inner GEMM: quarter kq of K'=256 interleaved ----
        a0 = a1 = a2 = a3 = 0ull;
        {
            const ulonglong2* h0 = (const ulonglong2*)(sh_xh + 0 * 272 + ib);
            const ulonglong2* h1 = (const ulonglong2*)(sh_xh + 1 * 272 + ib);
            const ulonglong2* h2 = (const ulonglong2*)(sh_xh + 2 * 272 + ib);
            const ulonglong2* h3 = (const ulonglong2*)(sh_xh + 3 * 272 + ib);
#pragma unroll
            for (int q2 = 0; q2 < 16; q2++) {
                ulonglong2 x0 = h0[q2], x1 = h1[q2], x2 = h2[q2], x3 = h3[q2];
                unsigned long long wA = wi[2 * q2], wB = wi[2 * q2 + 1];
                ffma2(a0, x0.x, wA); ffma2(a0, x0.y, wB);
                ffma2(a1, x1.x, wA); ffma2(a1, x1.y, wB);
                ffma2(a2, x2.x, wA); ffma2(a2, x2.y, wB);
                ffma2(a3, x3.x, wA); ffma2(a3, x3.y, wB);
            }
        }
        {
            float s0 = sum2(a0), s1 = sum2(a1), s2 = sum2(a2), s3 = sum2(a3);
            s0 += __shfl_xor_sync(0xffffffffu, s0, 1);
            s1 += __shfl_xor_sync(0xffffffffu, s1, 1);
            s2 += __shfl_xor_sync(0xffffffffu, s2, 1);
            s3 += __shfl_xor_sync(0xffffffffu, s3, 1);
            s0 += __shfl_xor_sync(0xffffffffu, s0, 2);
            s1 += __shfl_xor_sync(0xffffffffu, s1, 2);
            s2 += __shfl_xor_sync(0xffffffffu, s2, 2);
            s3 += __shfl_xor_sync(0xffffffffu, s3, 2);
            float sv = (kq == 0) ? s0 : ((kq == 1) ? s1 : ((kq == 2) ? s2 : s3));
            sg[kq * 128 + sgi] = sv + bin;
        }
        __syncthreads();

        // ---- elementwise 2: update state; own h local, 3 peers st.async ----
        if (t < 128) {
            float4 gv = *(const float4*)(sg + bl * 128 + hc * 4);  // {ii, fi, oi, gg}
            float ii = sigf(gv.x);
            float fi = sigf(gv.y);
            float oi = sigf(gv.z);
            float gg = tanhf_fast(gv.w);
            cn_reg = fi * cn_reg + ii * gg;
            c_reg  = oi * tanhf_fast(cn_reg);
            float hnew = o_reg * tanhf_fast(c_reg);
            sh_h[loc_h] = hnew;
#pragma unroll
            for (int r = 0; r < CPG; r++)
                if (r != (int)cs)
                    st_async_f32(ptab[r * 4 + 1] + offb_h, ptab[r * 4 + 3], hnew);
            g_hs[((size_t)s * BATCH + g * BG + bl) * HID + h_own] = hnew;
        }
        __syncthreads();   // own h visible
        MBAR_WAIT(bh_loc, par);
        if (t == 0) MBAR_ARM(bh_loc, 1536u);
    }
    CLUSTER_SYNC_();
}

// ---- Kernel 3: out[b][s][o] = b_lin[o] + sum_h hs[s][b][h] * W_lin[o][h] ----
__global__ __launch_bounds__(256) void out_kernel(const float* __restrict__ Wl,
                                                  const float* __restrict__ bl,
                                                  float* __restrict__ out) {
    extern __shared__ float sm[];
    float* hsb = sm;               // transposed [h][b], pad 136
    float* wls = sm + 128 * 136;   // [h][o] pad 65

    const int s = blockIdx.x;
    const int t = threadIdx.x;
    const int o = t & 63;
    const int b0 = (t >> 6) * 32;

    const float* src = g_hs + (size_t)s * BATCH * HID;   // [b][h]
    for (int q = t; q < 16384; q += 256) {
        int b = q >> 7, h = q & 127;
        hsb[h * 136 + b] = src[q];
    }
    for (int q = t; q < 8192; q += 256) {
        int oo = q >> 7, k = q & 127;
        wls[k * 65 + oo] = Wl[q];
    }
    __syncthreads();

    float acc[32];
#pragma unroll
    for (int jj = 0; jj < 32; jj++) acc[jj] = 0.f;
#pragma unroll 2
    for (int k = 0; k < HID; k++) {
        float wv = wls[k * 65 + o];
        const float4* hr = (const float4*)(hsb + k * 136 + b0);
#pragma unroll
        for (int j4 = 0; j4 < 8; j4++) {
            float4 hv = hr[j4];
            acc[4 * j4 + 0] = fmaf(hv.x, wv, acc[4 * j4 + 0]);
            acc[4 * j4 + 1] = fmaf(hv.y, wv, acc[4 * j4 + 1]);
            acc[4 * j4 + 2] = fmaf(hv.z, wv, acc[4 * j4 + 2]);
            acc[4 * j4 + 3] = fmaf(hv.w, wv, acc[4 * j4 + 3]);
        }
    }
    float bb = bl[o];
#pragma unroll
    for (int jj = 0; jj < 32; jj++) {
        out[((size_t)(b0 + jj) * S_LEN + s) * OUT_DIM + o] = acc[jj] + bb;
    }
}

extern "C" void kernel_launch(void* const* d_in, const int* in_sizes, int n_in,
                              void* d_out, int out_size) {
    const float* x      = (const float*)d_in[0];
    const float* Wx_out = (const float*)d_in[1];
    const float* Wh_out = (const float*)d_in[2];
    const float* b_out  = (const float*)d_in[3];
    const float* Wx_in  = (const float*)d_in[4];
    const float* Wh_in  = (const float*)d_in[5];
    const float* b_in   = (const float*)d_in[6];
    const float* W_lin  = (const float*)d_in[7];
    const float* b_lin  = (const float*)d_in[8];
    float* out = (float*)d_out;

    cudaFuncSetAttribute(out_kernel, cudaFuncAttributeMaxDynamicSharedMemorySize, OUT_SMEM);

    dummy_kernel<<<1, 32>>>(1);   // keep rec_kernel at ncu capture slot #4
    dummy_kernel<<<1, 32>>>(2);
    xproj_kernel<<<dim3(S_LEN, BATCH / 32), 256>>>(x, Wx_out, b_out);
    rec_kernel<<<NCTA, 512>>>(Wh_out, Wx_in, Wh_in, b_in);
    out_kernel<<<S_LEN, 256, OUT_SMEM>>>(W_lin, b_lin, out);
}

// round 12
// speedup vs baseline: 1.6053x; 1.6053x over previous
#include <cuda_runtime.h>
#include <cstdint>

#define S_LEN 2048
#define BATCH 128
#define IN_DIM 64
#define HID 128
#define G4 512
#define OUT_DIM 64
#define NGROUP 32
#define CPG 4
#define BG 4
#define NCTA (NGROUP * CPG)

// ---- static device scratch ----
__device__ float g_Xp[(size_t)S_LEN * BATCH * G4];   // [s][b][n]
__device__ float g_hs[(size_t)S_LEN * BATCH * HID];  // [s][b][h]
__device__ ulonglong2 g_woP[4 * 16 * 256];           // packed outer weights [cs][q2][t]
__device__ int g_dummy;

#define OUT_SMEM ((128 * 136 + 128 * 65) * 4)

__device__ __forceinline__ float sigf(float v) {
    return __fdividef(1.f, 1.f + __expf(-v));
}
__device__ __forceinline__ float tanhf_fast(float x) {
    float cx = fminf(fmaxf(x, -15.f), 15.f);
    float e = __expf(2.f * cx);
    return __fdividef(e - 1.f, e + 1.f);
}

__device__ __forceinline__ uint32_t smem_u32(const void* p) {
    uint32_t a;
    asm("{ .reg .u64 t; cvta.to.shared.u64 t, %1; cvt.u32.u64 %0, t; }" : "=r"(a) : "l"(p));
    return a;
}
__device__ __forceinline__ uint32_t mapa_u32(uint32_t local_addr, int rank) {
    uint32_t r;
    asm("mapa.shared::cluster.u32 %0, %1, %2;" : "=r"(r) : "r"(local_addr), "r"(rank));
    return r;
}
#define CLUSTER_SYNC_() do { \
    asm volatile("barrier.cluster.arrive.aligned;" ::: "memory"); \
    asm volatile("barrier.cluster.wait.aligned;" ::: "memory"); \
} while (0)

#define MBAR_INIT(addr, cnt) \
    asm volatile("mbarrier.init.shared.b64 [%0], %1;" :: "r"(addr), "r"(cnt) : "memory")
#define MBAR_ARM(addr, bytes) \
    asm volatile("mbarrier.arrive.expect_tx.shared.b64 _, [%0], %1;" :: "r"(addr), "r"(bytes) : "memory")
#define MBAR_WAIT(addr, parity) do { \
    asm volatile("{\n\t.reg .pred P1;\n\t" \
        "WAIT_%=:\n\t" \
        "mbarrier.try_wait.parity.acquire.cta.shared::cta.b64 P1, [%0], %1, 0x989680;\n\t" \
        "@P1 bra.uni DONE_%=;\n\t" \
        "bra.uni WAIT_%=;\n\t" \
        "DONE_%=:\n\t}" \
        :: "r"(addr), "r"(parity) : "memory"); \
} while (0)

__device__ __forceinline__ void st_async_f32(uint32_t daddr, uint32_t dmbar, float v) {
    asm volatile("st.async.shared::cluster.mbarrier::complete_tx::bytes.f32 [%0], %1, [%2];"
                 :: "r"(daddr), "f"(v), "r"(dmbar) : "memory");
}
__device__ __forceinline__ void st_async_v2f32(uint32_t daddr, uint32_t dmbar, float a, float b) {
    asm volatile("st.async.shared::cluster.mbarrier::complete_tx::bytes.v2.f32 [%0], {%1, %2}, [%3];"
                 :: "r"(daddr), "f"(a), "f"(b), "r"(dmbar) : "memory");
}

__device__ __forceinline__ void ffma2(unsigned long long& d, unsigned long long a, unsigned long long b) {
    asm("fma.rn.f32x2 %0, %1, %2, %0;" : "+l"(d) : "l"(a), "l"(b));
}
__device__ __forceinline__ unsigned long long pack2(float a, float b) {
    unsigned long long p;
    asm("mov.b64 %0, {%1, %2};" : "=l"(p) : "f"(a), "f"(b));
    return p;
}
__device__ __forceinline__ float sum2(unsigned long long p) {
    float lo, hi;
    asm("mov.b64 {%0, %1}, %2;" : "=f"(lo), "=f"(hi) : "l"(p));
    return lo + hi;
}

// ---- dummy: keeps rec_kernel at process launch #4 for ncu capture ----
__global__ void dummy_kernel(int v) {
    if (threadIdx.x == 0 && blockIdx.x == 0) g_dummy = v;
}

// ---- pack outer weights: g_woP[cs][q2][t] = {W[k],W[k+1]} , {W[k+2],W[k+3]} ----
__global__ void wpack_kernel(const float* __restrict__ Wh_out) {
    const int q2 = blockIdx.x;      // 0..15
    const int cs = blockIdx.y;      // 0..3
    const int t  = threadIdx.x;     // 0..255
    const int j  = t >> 1;
    const int kp = t & 1;
    const int gcol = (j >> 5) * 128 + cs * 32 + (j & 31);
    const int k = kp * 64 + 4 * q2;
    ulonglong2 v;
    v.x = pack2(Wh_out[(size_t)k * G4 + gcol],       Wh_out[(size_t)(k + 1) * G4 + gcol]);
    v.y = pack2(Wh_out[(size_t)(k + 2) * G4 + gcol], Wh_out[(size_t)(k + 3) * G4 + gcol]);
    g_woP[(cs * 16 + q2) * 256 + t] = v;
}

// ---- Kernel 1: Xp[s][b][n] = b_out[n] + sum_i x[b][i][s] * Wx_out[i][n] ----
__global__ __launch_bounds__(256) void xproj_kernel(const float* __restrict__ x,
                                                    const float* __restrict__ Wx,
                                                    const float* __restrict__ bo) {
    __shared__ float xs[IN_DIM * 33];
    const int s = blockIdx.x;
    const int b0 = blockIdx.y * 32;
    const int t = threadIdx.x;
    const int b = t & 31;
    const int n0 = (t >> 5) * 64;

    for (int q = t; q < 32 * IN_DIM; q += 256) {
        int bb = q >> 6, i = q & 63;
        xs[i * 33 + bb] = x[((size_t)(b0 + bb) * IN_DIM + i) * S_LEN + s];
    }
    __syncthreads();

    float acc[64];
#pragma unroll
    for (int j = 0; j < 64; j++) acc[j] = 0.f;
#pragma unroll 2
    for (int k = 0; k < IN_DIM; k++) {
        float xv = xs[k * 33 + b];
        const float4* wr = (const float4*)(Wx + (size_t)k * G4 + n0);
#pragma unroll
        for (int j4 = 0; j4 < 16; j4++) {
            float4 w = __ldg(&wr[j4]);
            acc[4 * j4 + 0] = fmaf(xv, w.x, acc[4 * j4 + 0]);
            acc[4 * j4 + 1] = fmaf(xv, w.y, acc[4 * j4 + 1]);
            acc[4 * j4 + 2] = fmaf(xv, w.z, acc[4 * j4 + 2]);
            acc[4 * j4 + 3] = fmaf(xv, w.w, acc[4 * j4 + 3]);
        }
    }
#pragma unroll
    for (int j = 0; j < 64; j++) {
        g_Xp[((size_t)s * BATCH + b0 + b) * G4 + n0 + j] = acc[j] + __ldg(&bo[n0 + j]);
    }
}

// ---- Kernel 2: persistent recurrence; cluster of 4 CTAs = 1 group (4 batch rows).
//      Inner weights register-resident; outer weights streamed from packed
//      L1-resident global (frees 64 regs for LDS pipelining). R7 sync protocol. ----
__global__ __launch_bounds__(256, 1) __cluster_dims__(CPG, 1, 1)
void rec_kernel(const float* __restrict__ Wx_in,
                const float* __restrict__ Wh_in,
                const float* __restrict__ b_in) {
    __shared__ __align__(16) float sh_h[BG * 2 * 68];     // staged h  [r][2 x 68]
    __shared__ __align__(16) float sh_xh[BG * 4 * 68];    // staged xh [r][4 x 68] (k'=2h interleave)
    __shared__ float sg[BG * 128];                        // gates [r][j]
    __shared__ __align__(8) unsigned long long mbars[2];  // [0]=xh, [1]=h
    __shared__ uint32_t ptab[CPG * 4];                    // per rank: xh, h, bx, bh

    const int cta = blockIdx.x;
    const int g   = cta >> 2;
    const int t   = threadIdx.x;
    const int j   = t >> 1;            // gate column 0..127
    const int kp  = t & 1;             // K-half
    uint32_t cs;
    asm("mov.u32 %0, %%cluster_ctarank;" : "=r"(cs));
    const int gcol = (j >> 5) * 128 + (int)cs * 32 + (j & 31);

    // ---- inner weights register-resident; outer weights via packed L1 buffer ----
    unsigned long long wi[64];   // inner: k' = kp*128 + 2q -> {Wx_in[h], Wh_in[h]}, h = kp*64 + q
    {
        const int hh0 = kp * 64;
#pragma unroll
        for (int q = 0; q < 64; q++)
            wi[q] = pack2(Wx_in[(size_t)(hh0 + q) * G4 + gcol],
                          Wh_in[(size_t)(hh0 + q) * G4 + gcol]);
    }
    const ulonglong2* wop = g_woP + (int)cs * (16 * 256) + t;   // [q2*256] stride
    const float bin = b_in[gcol];

    // peer address table + mbarrier init/arm
    if (t < CPG) {
        ptab[t * 4 + 0] = mapa_u32(smem_u32(sh_xh), t);
        ptab[t * 4 + 1] = mapa_u32(smem_u32(sh_h), t);
        ptab[t * 4 + 2] = mapa_u32(smem_u32(&mbars[0]), t);
        ptab[t * 4 + 3] = mapa_u32(smem_u32(&mbars[1]), t);
    }
    const uint32_t bx_loc = smem_u32(&mbars[0]);
    const uint32_t bh_loc = smem_u32(&mbars[1]);
    if (t == 0) {
        MBAR_INIT(bx_loc, 1);
        MBAR_INIT(bh_loc, 1);
        MBAR_ARM(bx_loc, 4096u);   // 4 ranks x 128 x 8B
        MBAR_ARM(bh_loc, 2048u);   // 4 ranks x 128 x 4B
    }
    for (int q = t; q < BG * 2 * 68; q += 256) sh_h[q] = 0.f;  // h0 = 0
    __syncthreads();
    CLUSTER_SYNC_();   // all peers' mbars initialized+armed before any st.async

    // owner role (t < 128): batch row bl, own hidden col
    const int bl = t >> 5, hc = t & 31;
    const int h_own = (int)cs * 32 + hc;
    const int kxi = 2 * h_own;
    const uint32_t offb_x = (uint32_t)(bl * 272 + (kxi >> 6) * 68 + (kxi & 63)) * 4u;
    const uint32_t offb_h = (uint32_t)(bl * 136 + (h_own >> 6) * 68 + (h_own & 63)) * 4u;
    float c_reg = 0.f, cn_reg = 0.f, o_reg = 0.f;

    const float* xp_base = g_Xp + (size_t)(g * BG) * G4 + gcol + (size_t)(kp * 2) * G4;

    for (int s = 0; s < S_LEN; s++) {
        const uint32_t par = (uint32_t)(s & 1);
        const float* xp = xp_base + (size_t)s * BATCH * G4;
        float xpa = __ldcs(xp), xpb = __ldcs(xp + G4);

        // ---- outer GEMM: K-half kp, 4 rows; outer weights streamed via L1 ----
        unsigned long long a0 = 0ull, a1 = 0ull, a2 = 0ull, a3 = 0ull;
        {
            const ulonglong2* h0 = (const ulonglong2*)(sh_h + 0 * 136 + kp * 68);
            const ulonglong2* h1 = (const ulonglong2*)(sh_h + 1 * 136 + kp * 68);
            const ulonglong2* h2 = (const ulonglong2*)(sh_h + 2 * 136 + kp * 68);
            const ulonglong2* h3 = (const ulonglong2*)(sh_h + 3 * 136 + kp * 68);
#pragma unroll
            for (int q2 = 0; q2 < 16; q2++) {
                ulonglong2 w = __ldg(&wop[q2 * 256]);
                ulonglong2 x0 = h0[q2], x1 = h1[q2], x2 = h2[q2], x3 = h3[q2];
                ffma2(a0, x0.x, w.x); ffma2(a0, x0.y, w.y);
                ffma2(a1, x1.x, w.x); ffma2(a1, x1.y, w.y);
                ffma2(a2, x2.x, w.x); ffma2(a2, x2.y, w.y);
                ffma2(a3, x3.x, w.x); ffma2(a3, x3.y, w.y);
            }
        }
        {
            float s0 = sum2(a0), s1 = sum2(a1), s2 = sum2(a2), s3 = sum2(a3);
            s0 += __shfl_xor_sync(0xffffffffu, s0, 1);
            s1 += __shfl_xor_sync(0xffffffffu, s1, 1);
            s2 += __shfl_xor_sync(0xffffffffu, s2, 1);
            s3 += __shfl_xor_sync(0xffffffffu, s3, 1);
            if (kp == 0) { sg[0 * 128 + j] = s0 + xpa; sg[1 * 128 + j] = s1 + xpb; }
            else         { sg[2 * 128 + j] = s2 + xpa; sg[3 * 128 + j] = s3 + xpb; }
        }
        __syncthreads();

        // ---- elementwise 1: push interleaved (x_in, h_in) to all 4 ranks ----
        if (t < 128) {
            float i_ = sigf(sg[bl * 128 + hc]);
            float f_ = sigf(sg[bl * 128 + 32 + hc]);
            o_reg    = sigf(sg[bl * 128 + 64 + hc]);
            float g_ = tanhf_fast(sg[bl * 128 + 96 + hc]);
            float xin = i_ * g_;
            float hin = f_ * c_reg;
#pragma unroll
            for (int r = 0; r < CPG; r++)
                st_async_v2f32(ptab[r * 4 + 0] + offb_x, ptab[r * 4 + 2], xin, hin);
        }
        MBAR_WAIT(bx_loc, par);
        if (t == 0) MBAR_ARM(bx_loc, 4096u);

        // ---- inner GEMM: K'=256 interleaved, half per kp ----
        a0 = a1 = a2 = a3 = 0ull;
        {
            const ulonglong2* h0 = (const ulonglong2*)(sh_xh + 0 * 272 + 2 * kp * 68);
            const ulonglong2* h1 = (const ulonglong2*)(sh_xh + 1 * 272 + 2 * kp * 68);
            const ulonglong2* h2 = (const ulonglong2*)(sh_xh + 2 * 272 + 2 * kp * 68);
            const ulonglong2* h3 = (const ulonglong2*)(sh_xh + 3 * 272 + 2 * kp * 68);
#pragma unroll
            for (int q2 = 0; q2 < 16; q2++) {
                ulonglong2 x0 = h0[q2], x1 = h1[q2], x2 = h2[q2], x3 = h3[q2];
                unsigned long long wA = wi[2 * q2], wB = wi[2 * q2 + 1];
                ffma2(a0, x0.x, wA); ffma2(a0, x0.y, wB);
                ffma2(a1, x1.x, wA); ffma2(a1, x1.y, wB);
                ffma2(a2, x2.x, wA); ffma2(a2, x2.y, wB);
                ffma2(a3, x3.x, wA); ffma2(a3, x3.y, wB);
            }
#pragma unroll
            for (int q2 = 0; q2 < 16; q2++) {
                ulonglong2 x0 = h0[17 + q2], x1 = h1[17 + q2], x2 = h2[17 + q2], x3 = h3[17 + q2];
                unsigned long long wA = wi[32 + 2 * q2], wB = wi[33 + 2 * q2];
                ffma2(a0, x0.x, wA); ffma2(a0, x0.y, wB);
                ffma2(a1, x1.x, wA); ffma2(a1, x1.y, wB);
                ffma2(a2, x2.x, wA); ffma2(a2, x2.y, wB);
                ffma2(a3, x3.x, wA); ffma2(a3, x3.y, wB);
            }
        }
        {
            float s0 = sum2(a0), s1 = sum2(a1), s2 = sum2(a2), s3 = sum2(a3);
            s0 += __shfl_xor_sync(0xffffffffu, s0, 1);
            s1 += __shfl_xor_sync(0xffffffffu, s1, 1);
            s2 += __shfl_xor_sync(0xffffffffu, s2, 1);
            s3 += __shfl_xor_sync(0xffffffffu, s3, 1);
            if (kp == 0) { sg[0 * 128 + j] = s0 + bin; sg[1 * 128 + j] = s1 + bin; }
            else         { sg[2 * 128 + j] = s2 + bin; sg[3 * 128 + j] = s3 + bin; }
        }
        __syncthreads();

        // ---- elementwise 2: update state; push h to all 4 ranks ----
        if (t < 128) {
            float ii = sigf(sg[bl * 128 + hc]);
            float fi = sigf(sg[bl * 128 + 32 + hc]);
            float oi = sigf(sg[bl * 128 + 64 + hc]);
            float gg = tanhf_fast(sg[bl * 128 + 96 + hc]);
            cn_reg = fi * cn_reg + ii * gg;
            c_reg  = oi * tanhf_fast(cn_reg);
            float hnew = o_reg * tanhf_fast(c_reg);
#pragma unroll
            for (int r = 0; r < CPG; r++)
                st_async_f32(ptab[r * 4 + 1] + offb_h, ptab[r * 4 + 3], hnew);
            g_hs[((size_t)s * BATCH + g * BG + bl) * HID + h_own] = hnew;
        }
        MBAR_WAIT(bh_loc, par);
        if (t == 0) MBAR_ARM(bh_loc, 2048u);
    }
    CLUSTER_SYNC_();
}

// ---- Kernel 3: out[b][s][o] = b_lin[o] + sum_h hs[s][b][h] * W_lin[o][h] ----
__global__ __launch_bounds__(256) void out_kernel(const float* __restrict__ Wl,
                                                  const float* __restrict__ bl,
                                                  float* __restrict__ out) {
    extern __shared__ float sm[];
    float* hsb = sm;               // transposed [h][b], pad 136
    float* wls = sm + 128 * 136;   // [h][o] pad 65

    const int s = blockIdx.x;
    const int t = threadIdx.x;
    const int o = t & 63;
    const int b0 = (t >> 6) * 32;

    const float* src = g_hs + (size_t)s * BATCH * HID;   // [b][h]
    for (int q = t; q < 16384; q += 256) {
        int b = q >> 7, h = q & 127;
        hsb[h * 136 + b] = src[q];
    }
    for (int q = t; q < 8192; q += 256) {
        int oo = q >> 7, k = q & 127;
        wls[k * 65 + oo] = Wl[q];
    }
    __syncthreads();

    float acc[32];
#pragma unroll
    for (int jj = 0; jj < 32; jj++) acc[jj] = 0.f;
#pragma unroll 2
    for (int k = 0; k < HID; k++) {
        float wv = wls[k * 65 + o];
        const float4* hr = (const float4*)(hsb + k * 136 + b0);
#pragma unroll
        for (int j4 = 0; j4 < 8; j4++) {
            float4 hv = hr[j4];
            acc[4 * j4 + 0] = fmaf(hv.x, wv, acc[4 * j4 + 0]);
            acc[4 * j4 + 1] = fmaf(hv.y, wv, acc[4 * j4 + 1]);
            acc[4 * j4 + 2] = fmaf(hv.z, wv, acc[4 * j4 + 2]);
            acc[4 * j4 + 3] = fmaf(hv.w, wv, acc[4 * j4 + 3]);
        }
    }
    float bb = bl[o];
#pragma unroll
    for (int jj = 0; jj < 32; jj++) {
        out[((size_t)(b0 + jj) * S_LEN + s) * OUT_DIM + o] = acc[jj] + bb;
    }
}

extern "C" void kernel_launch(void* const* d_in, const int* in_sizes, int n_in,
                              void* d_out, int out_size) {
    const float* x      = (const float*)d_in[0];
    const float* Wx_out = (const float*)d_in[1];
    const float* Wh_out = (const float*)d_in[2];
    const float* b_out  = (const float*)d_in[3];
    const float* Wx_in  = (const float*)d_in[4];
    const float* Wh_in  = (const float*)d_in[5];
    const float* b_in   = (const float*)d_in[6];
    const float* W_lin  = (const float*)d_in[7];
    const float* b_lin  = (const float*)d_in[8];
    float* out = (float*)d_out;

    cudaFuncSetAttribute(out_kernel, cudaFuncAttributeMaxDynamicSharedMemorySize, OUT_SMEM);

    dummy_kernel<<<1, 32>>>(1);                            // launch #1
    xproj_kernel<<<dim3(S_LEN, BATCH / 32), 256>>>(x, Wx_out, b_out);  // #2
    wpack_kernel<<<dim3(16, 4), 256>>>(Wh_out);            // #3
    rec_kernel<<<NCTA, 256>>>(Wx_in, Wh_in, b_in);         // #4 <- ncu slot
    out_kernel<<<S_LEN, 256, OUT_SMEM>>>(W_lin, b_lin, out);
}

// round 13
// speedup vs baseline: 1.7061x; 1.0628x over previous
#include <cuda_runtime.h>
#include <cstdint>

#define S_LEN 2048
#define BATCH 128
#define IN_DIM 64
#define HID 128
#define G4 512
#define OUT_DIM 64
#define NGROUP 32
#define CPG 4
#define BG 4
#define NCTA (NGROUP * CPG)

// ---- static device scratch ----
__device__ float g_Xp[(size_t)S_LEN * BATCH * G4];   // [s][b][n]
__device__ float g_hs[(size_t)S_LEN * BATCH * HID];  // [s][b][h]
__device__ int g_dummy;

#define OUT_SMEM ((128 * 136 + 128 * 65) * 4)

__device__ __forceinline__ float sigf(float v) {
    return __fdividef(1.f, 1.f + __expf(-v));
}
__device__ __forceinline__ float tanhf_fast(float x) {
    float cx = fminf(fmaxf(x, -15.f), 15.f);
    float e = __expf(2.f * cx);
    return __fdividef(e - 1.f, e + 1.f);
}

__device__ __forceinline__ uint32_t smem_u32(const void* p) {
    uint32_t a;
    asm("{ .reg .u64 t; cvta.to.shared.u64 t, %1; cvt.u32.u64 %0, t; }" : "=r"(a) : "l"(p));
    return a;
}
__device__ __forceinline__ uint32_t mapa_u32(uint32_t local_addr, int rank) {
    uint32_t r;
    asm("mapa.shared::cluster.u32 %0, %1, %2;" : "=r"(r) : "r"(local_addr), "r"(rank));
    return r;
}
#define CLUSTER_SYNC_() do { \
    asm volatile("barrier.cluster.arrive.aligned;" ::: "memory"); \
    asm volatile("barrier.cluster.wait.aligned;" ::: "memory"); \
} while (0)

#define MBAR_INIT(addr, cnt) \
    asm volatile("mbarrier.init.shared.b64 [%0], %1;" :: "r"(addr), "r"(cnt) : "memory")
#define MBAR_ARM(addr, bytes) \
    asm volatile("mbarrier.arrive.expect_tx.shared.b64 _, [%0], %1;" :: "r"(addr), "r"(bytes) : "memory")
#define MBAR_WAIT(addr, parity) do { \
    asm volatile("{\n\t.reg .pred P1;\n\t" \
        "WAIT_%=:\n\t" \
        "mbarrier.try_wait.parity.acquire.cta.shared::cta.b64 P1, [%0], %1, 0x989680;\n\t" \
        "@P1 bra.uni DONE_%=;\n\t" \
        "bra.uni WAIT_%=;\n\t" \
        "DONE_%=:\n\t}" \
        :: "r"(addr), "r"(parity) : "memory"); \
} while (0)

__device__ __forceinline__ void st_async_f32(uint32_t daddr, uint32_t dmbar, float v) {
    asm volatile("st.async.shared::cluster.mbarrier::complete_tx::bytes.f32 [%0], %1, [%2];"
                 :: "r"(daddr), "f"(v), "r"(dmbar) : "memory");
}
__device__ __forceinline__ void st_async_v2f32(uint32_t daddr, uint32_t dmbar, float a, float b) {
    asm volatile("st.async.shared::cluster.mbarrier::complete_tx::bytes.v2.f32 [%0], {%1, %2}, [%3];"
                 :: "r"(daddr), "f"(a), "f"(b), "r"(dmbar) : "memory");
}

__device__ __forceinline__ void ffma2(unsigned long long& d, unsigned long long a, unsigned long long b) {
    asm("fma.rn.f32x2 %0, %1, %2, %0;" : "+l"(d) : "l"(a), "l"(b));
}
__device__ __forceinline__ unsigned long long pack2(float a, float b) {
    unsigned long long p;
    asm("mov.b64 %0, {%1, %2};" : "=l"(p) : "f"(a), "f"(b));
    return p;
}
__device__ __forceinline__ float sum2(unsigned long long p) {
    float lo, hi;
    asm("mov.b64 {%0, %1}, %2;" : "=f"(lo), "=f"(hi) : "l"(p));
    return lo + hi;
}

// ---- dummy: keeps rec_kernel at process launch #4 for ncu capture ----
__global__ void dummy_kernel(int v) {
    if (threadIdx.x == 0 && blockIdx.x == 0) g_dummy = v;
}

// ---- Kernel 1: Xp[s][b][n] = b_out[n] + sum_i x[b][i][s] * Wx_out[i][n] ----
__global__ __launch_bounds__(256) void xproj_kernel(const float* __restrict__ x,
                                                    const float* __restrict__ Wx,
                                                    const float* __restrict__ bo) {
    __shared__ float xs[IN_DIM * 33];
    const int s = blockIdx.x;
    const int b0 = blockIdx.y * 32;
    const int t = threadIdx.x;
    const int b = t & 31;
    const int n0 = (t >> 5) * 64;

    for (int q = t; q < 32 * IN_DIM; q += 256) {
        int bb = q >> 6, i = q & 63;
        xs[i * 33 + bb] = x[((size_t)(b0 + bb) * IN_DIM + i) * S_LEN + s];
    }
    __syncthreads();

    float acc[64];
#pragma unroll
    for (int j = 0; j < 64; j++) acc[j] = 0.f;
#pragma unroll 2
    for (int k = 0; k < IN_DIM; k++) {
        float xv = xs[k * 33 + b];
        const float4* wr = (const float4*)(Wx + (size_t)k * G4 + n0);
#pragma unroll
        for (int j4 = 0; j4 < 16; j4++) {
            float4 w = __ldg(&wr[j4]);
            acc[4 * j4 + 0] = fmaf(xv, w.x, acc[4 * j4 + 0]);
            acc[4 * j4 + 1] = fmaf(xv, w.y, acc[4 * j4 + 1]);
            acc[4 * j4 + 2] = fmaf(xv, w.z, acc[4 * j4 + 2]);
            acc[4 * j4 + 3] = fmaf(xv, w.w, acc[4 * j4 + 3]);
        }
    }
#pragma unroll
    for (int j = 0; j < 64; j++) {
        g_Xp[((size_t)s * BATCH + b0 + b) * G4 + n0 + j] = acc[j] + __ldg(&bo[n0 + j]);
    }
}

// ---- Kernel 2: persistent recurrence; cluster of 4 CTAs = 1 group (4 batch rows).
//      Thread (p = t>>2, q = t&3): 2 gate cols {p, p+64}, K-quarter q.
//      2x arithmetic intensity per LDS; 8-way broadcast, conflict-free layouts. ----
__global__ __launch_bounds__(256, 1) __cluster_dims__(CPG, 1, 1)
void rec_kernel(const float* __restrict__ Wh_out,
                const float* __restrict__ Wx_in,
                const float* __restrict__ Wh_in,
                const float* __restrict__ b_in) {
    __shared__ __align__(16) float sh_h[BG * 4 * 36];     // staged h  [r][4 x 36] (quarters of 32 + 4 pad)
    __shared__ __align__(16) float sh_xh[BG * 4 * 68];    // staged xh [r][4 x 68] (k'=2h interleave)
    __shared__ float sg[BG * 132];                        // gates [r][j], stride 132
    __shared__ __align__(8) unsigned long long mbars[2];  // [0]=xh, [1]=h
    __shared__ uint32_t ptab[CPG * 4];                    // per rank: xh, h, bx, bh

    const int cta = blockIdx.x;
    const int g   = cta >> 2;
    const int t   = threadIdx.x;
    const int p   = t >> 2;            // column pair 0..63
    const int q   = t & 3;             // K-quarter
    uint32_t cs;
    asm("mov.u32 %0, %%cluster_ctarank;" : "=r"(cs));
    const int c0 = p, c1 = p + 64;
    const int gcol0 = (c0 >> 5) * 128 + (int)cs * 32 + (c0 & 31);
    const int gcol1 = (c1 >> 5) * 128 + (int)cs * 32 + (c1 & 31);

    // ---- register-resident weights: 2 cols x K-quarter ----
    unsigned long long wo0[16], wo1[16];   // outer: k = q*32 + 2i
    unsigned long long wi0[32], wi1[32];   // inner: h = q*32 + i -> {Wx_in[h], Wh_in[h]}
    {
        const float* wb = Wh_out + (size_t)(q * 32) * G4;
#pragma unroll
        for (int i = 0; i < 16; i++) {
            wo0[i] = pack2(wb[(size_t)(2 * i) * G4 + gcol0], wb[(size_t)(2 * i + 1) * G4 + gcol0]);
            wo1[i] = pack2(wb[(size_t)(2 * i) * G4 + gcol1], wb[(size_t)(2 * i + 1) * G4 + gcol1]);
        }
        const int h0i = q * 32;
#pragma unroll
        for (int i = 0; i < 32; i++) {
            wi0[i] = pack2(Wx_in[(size_t)(h0i + i) * G4 + gcol0], Wh_in[(size_t)(h0i + i) * G4 + gcol0]);
            wi1[i] = pack2(Wx_in[(size_t)(h0i + i) * G4 + gcol1], Wh_in[(size_t)(h0i + i) * G4 + gcol1]);
        }
    }
    const float bin0 = b_in[gcol0];
    const float bin1 = b_in[gcol1];

    // peer address table + mbarrier init/arm
    if (t < CPG) {
        ptab[t * 4 + 0] = mapa_u32(smem_u32(sh_xh), t);
        ptab[t * 4 + 1] = mapa_u32(smem_u32(sh_h), t);
        ptab[t * 4 + 2] = mapa_u32(smem_u32(&mbars[0]), t);
        ptab[t * 4 + 3] = mapa_u32(smem_u32(&mbars[1]), t);
    }
    const uint32_t bx_loc = smem_u32(&mbars[0]);
    const uint32_t bh_loc = smem_u32(&mbars[1]);
    if (t == 0) {
        MBAR_INIT(bx_loc, 1);
        MBAR_INIT(bh_loc, 1);
        MBAR_ARM(bx_loc, 4096u);   // 4 ranks x 128 x 8B
        MBAR_ARM(bh_loc, 2048u);   // 4 ranks x 128 x 4B
    }
    for (int qq = t; qq < BG * 4 * 36; qq += 256) sh_h[qq] = 0.f;  // h0 = 0
    __syncthreads();
    CLUSTER_SYNC_();   // all peers' mbars initialized+armed before any st.async

    // owner role (t < 128): batch row bl, own hidden col
    const int bl = t >> 5, hc = t & 31;
    const int h_own = (int)cs * 32 + hc;
    const int kxi = 2 * h_own;
    const uint32_t offb_x = (uint32_t)(bl * 272 + (kxi >> 6) * 68 + (kxi & 63)) * 4u;
    const uint32_t offb_h = (uint32_t)(bl * 144 + (h_own >> 5) * 36 + (h_own & 31)) * 4u;
    float c_reg = 0.f, cn_reg = 0.f, o_reg = 0.f;

    // Xp prefetch pointers: batch row g*4+q, cols gcol0/gcol1
    const float* xpp0 = g_Xp + (size_t)(g * BG + q) * G4 + gcol0;
    const float* xpp1 = g_Xp + (size_t)(g * BG + q) * G4 + gcol1;

    for (int s = 0; s < S_LEN; s++) {
        const uint32_t par = (uint32_t)(s & 1);
        float xpa = __ldcs(xpp0 + (size_t)s * BATCH * G4);
        float xpb = __ldcs(xpp1 + (size_t)s * BATCH * G4);

        // ---- outer GEMM: quarter q, 2 cols, 4 rows ----
        unsigned long long a00 = 0ull, a01 = 0ull, a02 = 0ull, a03 = 0ull;
        unsigned long long a10 = 0ull, a11 = 0ull, a12 = 0ull, a13 = 0ull;
        {
            const ulonglong2* h0 = (const ulonglong2*)(sh_h + 0 * 144 + q * 36);
            const ulonglong2* h1 = (const ulonglong2*)(sh_h + 1 * 144 + q * 36);
            const ulonglong2* h2 = (const ulonglong2*)(sh_h + 2 * 144 + q * 36);
            const ulonglong2* h3 = (const ulonglong2*)(sh_h + 3 * 144 + q * 36);
#pragma unroll
            for (int u = 0; u < 8; u++) {
                ulonglong2 x0 = h0[u], x1 = h1[u], x2 = h2[u], x3 = h3[u];
                unsigned long long wA = wo0[2 * u], wB = wo0[2 * u + 1];
                unsigned long long wC = wo1[2 * u], wD = wo1[2 * u + 1];
                ffma2(a00, x0.x, wA); ffma2(a00, x0.y, wB);
                ffma2(a01, x1.x, wA); ffma2(a01, x1.y, wB);
                ffma2(a02, x2.x, wA); ffma2(a02, x2.y, wB);
                ffma2(a03, x3.x, wA); ffma2(a03, x3.y, wB);
                ffma2(a10, x0.x, wC); ffma2(a10, x0.y, wD);
                ffma2(a11, x1.x, wC); ffma2(a11, x1.y, wD);
                ffma2(a12, x2.x, wC); ffma2(a12, x2.y, wD);
                ffma2(a13, x3.x, wC); ffma2(a13, x3.y, wD);
            }
        }
        {
            float r00 = sum2(a00), r01 = sum2(a01), r02 = sum2(a02), r03 = sum2(a03);
            float r10 = sum2(a10), r11 = sum2(a11), r12 = sum2(a12), r13 = sum2(a13);
            r00 += __shfl_xor_sync(0xffffffffu, r00, 1); r01 += __shfl_xor_sync(0xffffffffu, r01, 1);
            r02 += __shfl_xor_sync(0xffffffffu, r02, 1); r03 += __shfl_xor_sync(0xffffffffu, r03, 1);
            r10 += __shfl_xor_sync(0xffffffffu, r10, 1); r11 += __shfl_xor_sync(0xffffffffu, r11, 1);
            r12 += __shfl_xor_sync(0xffffffffu, r12, 1); r13 += __shfl_xor_sync(0xffffffffu, r13, 1);
            r00 += __shfl_xor_sync(0xffffffffu, r00, 2); r01 += __shfl_xor_sync(0xffffffffu, r01, 2);
            r02 += __shfl_xor_sync(0xffffffffu, r02, 2); r03 += __shfl_xor_sync(0xffffffffu, r03, 2);
            r10 += __shfl_xor_sync(0xffffffffu, r10, 2); r11 += __shfl_xor_sync(0xffffffffu, r11, 2);
            r12 += __shfl_xor_sync(0xffffffffu, r12, 2); r13 += __shfl_xor_sync(0xffffffffu, r13, 2);
            float v0 = (q == 0) ? r00 : ((q == 1) ? r01 : ((q == 2) ? r02 : r03));
            float v1 = (q == 0) ? r10 : ((q == 1) ? r11 : ((q == 2) ? r12 : r13));
            sg[q * 132 + p]      = v0 + xpa;
            sg[q * 132 + p + 64] = v1 + xpb;
        }
        __syncthreads();

        // ---- elementwise 1: push interleaved (x_in, h_in) to all 4 ranks ----
        if (t < 128) {
            float i_ = sigf(sg[bl * 132 + hc]);
            float f_ = sigf(sg[bl * 132 + 32 + hc]);
            o_reg    = sigf(sg[bl * 132 + 64 + hc]);
            float g_ = tanhf_fast(sg[bl * 132 + 96 + hc]);
            float xin = i_ * g_;
            float hin = f_ * c_reg;
#pragma unroll
            for (int r = 0; r < CPG; r++)
                st_async_v2f32(ptab[r * 4 + 0] + offb_x, ptab[r * 4 + 2], xin, hin);
        }
        MBAR_WAIT(bx_loc, par);
        if (t == 0) MBAR_ARM(bx_loc, 4096u);

        // ---- inner GEMM: quarter q of K'=256 interleaved, 2 cols, 4 rows ----
        a00 = a01 = a02 = a03 = 0ull;
        a10 = a11 = a12 = a13 = 0ull;
        {
            const ulonglong2* h0 = (const ulonglong2*)(sh_xh + 0 * 272 + q * 68);
            const ulonglong2* h1 = (const ulonglong2*)(sh_xh + 1 * 272 + q * 68);
            const ulonglong2* h2 = (const ulonglong2*)(sh_xh + 2 * 272 + q * 68);
            const ulonglong2* h3 = (const ulonglong2*)(sh_xh + 3 * 272 + q * 68);
#pragma unroll
            for (int u = 0; u < 16; u++) {
                ulonglong2 x0 = h0[u], x1 = h1[u], x2 = h2[u], x3 = h3[u];
                unsigned long long wA = wi0[2 * u], wB = wi0[2 * u + 1];
                unsigned long long wC = wi1[2 * u], wD = wi1[2 * u + 1];
                ffma2(a00, x0.x, wA); ffma2(a00, x0.y, wB);
                ffma2(a01, x1.x, wA); ffma2(a01, x1.y, wB);
                ffma2(a02, x2.x, wA); ffma2(a02, x2.y, wB);
                ffma2(a03, x3.x, wA); ffma2(a03, x3.y, wB);
                ffma2(a10, x0.x, wC); ffma2(a10, x0.y, wD);
                ffma2(a11, x1.x, wC); ffma2(a11, x1.y, wD);
                ffma2(a12, x2.x, wC); ffma2(a12, x2.y, wD);
                ffma2(a13, x3.x, wC); ffma2(a13, x3.y, wD);
            }
        }
        {
            float r00 = sum2(a00), r01 = sum2(a01), r02 = sum2(a02), r03 = sum2(a03);
            float r10 = sum2(a10), r11 = sum2(a11), r12 = sum2(a12), r13 = sum2(a13);
            r00 += __shfl_xor_sync(0xffffffffu, r00, 1); r01 += __shfl_xor_sync(0xffffffffu, r01, 1);
            r02 += __shfl_xor_sync(0xffffffffu, r02, 1); r03 += __shfl_xor_sync(0xffffffffu, r03, 1);
            r10 += __shfl_xor_sync(0xffffffffu, r10, 1); r11 += __shfl_xor_sync(0xffffffffu, r11, 1);
            r12 += __shfl_xor_sync(0xffffffffu, r12, 1); r13 += __shfl_xor_sync(0xffffffffu, r13, 1);
            r00 += __shfl_xor_sync(0xffffffffu, r00, 2); r01 += __shfl_xor_sync(0xffffffffu, r01, 2);
            r02 += __shfl_xor_sync(0xffffffffu, r02, 2); r03 += __shfl_xor_sync(0xffffffffu, r03, 2);
            r10 += __shfl_xor_sync(0xffffffffu, r10, 2); r11 += __shfl_xor_sync(0xffffffffu, r11, 2);
            r12 += __shfl_xor_sync(0xffffffffu, r12, 2); r13 += __shfl_xor_sync(0xffffffffu, r13, 2);
            float v0 = (q == 0) ? r00 : ((q == 1) ? r01 : ((q == 2) ? r02 : r03));
            float v1 = (q == 0) ? r10 : ((q == 1) ? r11 : ((q == 2) ? r12 : r13));
            sg[q * 132 + p]      = v0 + bin0;
            sg[q * 132 + p + 64] = v1 + bin1;
        }
        __syncthreads();

        // ---- elementwise 2: update state; push h to all 4 ranks ----
        if (t < 128) {
            float ii = sigf(sg[bl * 132 + hc]);
            float fi = sigf(sg[bl * 132 + 32 + hc]);
            float oi = sigf(sg[bl * 132 + 64 + hc]);
            float gg = tanhf_fast(sg[bl * 132 + 96 + hc]);
            cn_reg = fi * cn_reg + ii * gg;
            c_reg  = oi * tanhf_fast(cn_reg);
            float hnew = o_reg * tanhf_fast(c_reg);
#pragma unroll
            for (int r = 0; r < CPG; r++)
                st_async_f32(ptab[r * 4 + 1] + offb_h, ptab[r * 4 + 3], hnew);
            g_hs[((size_t)s * BATCH + g * BG + bl) * HID + h_own] = hnew;
        }
        MBAR_WAIT(bh_loc, par);
        if (t == 0) MBAR_ARM(bh_loc, 2048u);
    }
    CLUSTER_SYNC_();
}

// ---- Kernel 3: out[b][s][o] = b_lin[o] + sum_h hs[s][b][h] * W_lin[o][h] ----
__global__ __launch_bounds__(256) void out_kernel(const float* __restrict__ Wl,
                                                  const float* __restrict__ bl,
                                                  float* __restrict__ out) {
    extern __shared__ float sm[];
    float* hsb = sm;               // transposed [h][b], pad 136
    float* wls = sm + 128 * 136;   // [h][o] pad 65

    const int s = blockIdx.x;
    const int t = threadIdx.x;
    const int o = t & 63;
    const int b0 = (t >> 6) * 32;

    const float* src = g_hs + (size_t)s * BATCH * HID;   // [b][h]
    for (int q = t; q < 16384; q += 256) {
        int b = q >> 7, h = q & 127;
        hsb[h * 136 + b] = src[q];
    }
    for (int q = t; q < 8192; q += 256) {
        int oo = q >> 7, k = q & 127;
        wls[k * 65 + oo] = Wl[q];
    }
    __syncthreads();

    float acc[32];
#pragma unroll
    for (int jj = 0; jj < 32; jj++) acc[jj] = 0.f;
#pragma unroll 2
    for (int k = 0; k < HID; k++) {
        float wv = wls[k * 65 + o];
        const float4* hr = (const float4*)(hsb + k * 136 + b0);
#pragma unroll
        for (int j4 = 0; j4 < 8; j4++) {
            float4 hv = hr[j4];
            acc[4 * j4 + 0] = fmaf(hv.x, wv, acc[4 * j4 + 0]);
            acc[4 * j4 + 1] = fmaf(hv.y, wv, acc[4 * j4 + 1]);
            acc[4 * j4 + 2] = fmaf(hv.z, wv, acc[4 * j4 + 2]);
            acc[4 * j4 + 3] = fmaf(hv.w, wv, acc[4 * j4 + 3]);
        }
    }
    float bb = bl[o];
#pragma unroll
    for (int jj = 0; jj < 32; jj++) {
        out[((size_t)(b0 + jj) * S_LEN + s) * OUT_DIM + o] = acc[jj] + bb;
    }
}

extern "C" void kernel_launch(void* const* d_in, const int* in_sizes, int n_in,
                              void* d_out, int out_size) {
    const float* x      = (const float*)d_in[0];
    const float* Wx_out = (const float*)d_in[1];
    const float* Wh_out = (const float*)d_in[2];
    const float* b_out  = (const float*)d_in[3];
    const float* Wx_in  = (const float*)d_in[4];
    const float* Wh_in  = (const float*)d_in[5];
    const float* b_in   = (const float*)d_in[6];
    const float* W_lin  = (const float*)d_in[7];
    const float* b_lin  = (const float*)d_in[8];
    float* out = (float*)d_out;

    cudaFuncSetAttribute(out_kernel, cudaFuncAttributeMaxDynamicSharedMemorySize, OUT_SMEM);

    dummy_kernel<<<1, 32>>>(1);                            // launch #1
    dummy_kernel<<<1, 32>>>(2);                            // launch #2
    xproj_kernel<<<dim3(S_LEN, BATCH / 32), 256>>>(x, Wx_out, b_out);  // #3
    rec_kernel<<<NCTA, 256>>>(Wh_out, Wx_in, Wh_in, b_in);             // #4 <- ncu slot
    out_kernel<<<S_LEN, 256, OUT_SMEM>>>(W_lin, b_lin, out);
}